// round 12
// baseline (speedup 1.0000x reference)
#include <cuda_runtime.h>
#include <cuda_fp16.h>
#include <math.h>
#include <stdint.h>

#define N_TOK 2048
#define DIM   1024
#define DE    512
#define DS    1024
#define NE    8
#define NSLOT (N_TOK * 2)
#define ECAP  2048

// ----------------- scratch (device globals; no allocs) -----------------
__device__ int   d_ecnt[NE];                 // zeroed via cudaMemsetAsync
__device__ int   d_etok[NE * ECAP];
__device__ float d_ewt [NE * ECAP];
__device__ int   d_slot[NSLOT];

__device__ __half d_x  [N_TOK * DIM];
__device__ __half d_Wgs[DS * DIM];           // weights fp16, [N][K]
__device__ __half d_Wus[DS * DIM];
__device__ __half d_Wds[DIM * DS];
__device__ __half d_Wge[NE * DE * DIM];
__device__ __half d_Wue[NE * DE * DIM];
__device__ __half d_Wde[NE * DIM * DE];

__device__ __half d_Hs[N_TOK * DS];
__device__ __half d_Hr[NE * ECAP * DE];
__device__ float d_R [NE * ECAP * DIM];

// ----------------- asm helpers -----------------
__device__ __forceinline__ uint32_t sm2u32(const void* p) {
    uint32_t a;
    asm("{ .reg .u64 t; cvta.to.shared.u64 t, %1; cvt.u32.u64 %0, t; }" : "=r"(a) : "l"(p));
    return a;
}
#define SWZ(o) ((o) ^ (((o) >> 3) & 0x70))

#define CPA16(s, g)  asm volatile("cp.async.cg.shared.global [%0], [%1], 16;" :: "r"(s), "l"(g))
#define CPCOMMIT()   asm volatile("cp.async.commit_group;" ::: "memory")
#define CPWAIT1()    asm volatile("cp.async.wait_group 1;" ::: "memory")
#define CPWAIT0()    asm volatile("cp.async.wait_group 0;" ::: "memory")

#define LDMX4(r, a) \
    asm volatile("ldmatrix.sync.aligned.m8n8.x4.shared.b16 {%0,%1,%2,%3}, [%4];" \
        : "=r"((r)[0]), "=r"((r)[1]), "=r"((r)[2]), "=r"((r)[3]) : "r"(a))

#define MMAF16(c, a, b0, b1) \
    asm volatile("mma.sync.aligned.m16n8k16.row.col.f32.f16.f16.f32 " \
        "{%0,%1,%2,%3},{%4,%5,%6,%7},{%8,%9},{%0,%1,%2,%3};" \
        : "+f"((c)[0]), "+f"((c)[1]), "+f"((c)[2]), "+f"((c)[3]) \
        : "r"((a)[0]), "r"((a)[1]), "r"((a)[2]), "r"((a)[3]), "r"(b0), "r"(b1))

// ----------------- gate + convX + routing (fused) -----------------
__global__ void gate_kernel(const float* __restrict__ x, const float* __restrict__ Wg) {
    int n = blockIdx.x;
    int t = threadIdx.x;
    __shared__ float xs[DIM];
    __shared__ float logits[NE];
    float4 v = ((const float4*)(x + (size_t)n * DIM))[t];
    ((float4*)xs)[t] = v;
    {
        __half2 a, b;
        a.x = __float2half(v.x); a.y = __float2half(v.y);
        b.x = __float2half(v.z); b.y = __float2half(v.w);
        size_t o = (size_t)n * DIM + t * 4;
        *(__half2*)(d_x + o) = a; *(__half2*)(d_x + o + 2) = b;
    }
    __syncthreads();
    int w = t >> 5, l = t & 31;
    float s = 0.f;
    for (int d = l; d < DIM; d += 32) s += xs[d] * Wg[d * NE + w];
    #pragma unroll
    for (int o = 16; o; o >>= 1) s += __shfl_xor_sync(0xffffffffu, s, o);
    if (l == 0) logits[w] = s;
    __syncthreads();
    if (t == 0) {
        float mx = logits[0];
        #pragma unroll
        for (int e = 1; e < NE; e++) mx = fmaxf(mx, logits[e]);
        float p[NE], den = 0.f;
        #pragma unroll
        for (int e = 0; e < NE; e++) { p[e] = expf(logits[e] - mx); den += p[e]; }
        float inv = 1.f / den;
        int i0 = 0;
        #pragma unroll
        for (int e = 1; e < NE; e++) if (p[e] > p[i0]) i0 = e;
        int i1 = (i0 == 0) ? 1 : 0;
        #pragma unroll
        for (int e = 0; e < NE; e++) if (e != i0 && p[e] > p[i1]) i1 = e;
        int p0 = atomicAdd(&d_ecnt[i0], 1);
        int s0 = i0 * ECAP + p0;
        d_etok[s0] = n; d_ewt[s0] = p[i0] * inv; d_slot[2*n] = s0;
        int p1 = atomicAdd(&d_ecnt[i1], 1);
        int s1 = i1 * ECAP + p1;
        d_etok[s1] = n; d_ewt[s1] = p[i1] * inv; d_slot[2*n+1] = s1;
    }
}

// weight transposes, one launch: src [K][N] fp32 -> [N][K] fp16
__global__ void convT_all(const float* __restrict__ Wgs, const float* __restrict__ Wus,
                          const float* __restrict__ Wds, const float* __restrict__ Wge,
                          const float* __restrict__ Wue, const float* __restrict__ Wde) {
    int id = blockIdx.x;
    const float* src; __half* dh; int K, N, tile;
    if (id < 1024)      { src = Wgs; dh = d_Wgs; K = DIM; N = DS;  tile = id; }
    else if (id < 2048) { src = Wus; dh = d_Wus; K = DIM; N = DS;  tile = id - 1024; }
    else if (id < 3072) { src = Wds; dh = d_Wds; K = DS;  N = DIM; tile = id - 2048; }
    else if (id < 7168) {
        int l = id - 3072; int b = l >> 9; tile = l & 511; K = DIM; N = DE;
        src = Wge + (size_t)b * DIM * DE; dh = d_Wge + (size_t)b * DE * DIM;
    } else if (id < 11264) {
        int l = id - 7168; int b = l >> 9; tile = l & 511; K = DIM; N = DE;
        src = Wue + (size_t)b * DIM * DE; dh = d_Wue + (size_t)b * DE * DIM;
    } else {
        int l = id - 11264; int b = l >> 9; tile = l & 511; K = DE; N = DIM;
        src = Wde + (size_t)b * DE * DIM; dh = d_Wde + (size_t)b * DIM * DE;
    }
    int tilesX = N / 32;
    int n0 = (tile % tilesX) * 32, k0 = (tile / tilesX) * 32;
    __shared__ float t[32][33];
    int tx = threadIdx.x, ty = threadIdx.y;
    #pragma unroll
    for (int i = 0; i < 32; i += 8) t[ty + i][tx] = src[(size_t)(k0 + ty + i) * N + n0 + tx];
    __syncthreads();
    #pragma unroll
    for (int i = 0; i < 32; i += 8) {
        dh[(size_t)(n0 + ty + i) * K + k0 + tx] = __float2half(t[tx][ty + i]);
    }
}

__device__ __forceinline__ float silu(float g) { return g * (1.f / (1.f + expf(-g))); }

__global__ void combine_kernel(float* __restrict__ out) {
    int n = blockIdx.x;
    int t = threadIdx.x;
    int s0 = d_slot[2 * n], s1 = d_slot[2 * n + 1];
    float4* o4 = (float4*)(out + (size_t)n * DIM);
    const float4* r0 = (const float4*)(d_R + (size_t)s0 * DIM);
    const float4* r1 = (const float4*)(d_R + (size_t)s1 * DIM);
    float4 a = o4[t], b = r0[t], c = r1[t];
    a.x += b.x + c.x; a.y += b.y + c.y; a.z += b.z + c.z; a.w += b.w + c.w;
    o4[t] = a;
}

// ============================================================
// GEMMs: pure fp16. K-stage 128 (two 64-K sub-buffers, SW128 rows),
// 2-stage cp.async, 2 CTAs/SM, register fragment double-buffering.
// ============================================================

// ---------------- hidden GEMM ----------------
// CTA tile M64 x N64 per matrix (g,u); 8 warps 2x4, warp 32x16 per matrix.
// stage: [A 16K][BG 16K][BU 16K] = 48K, each 16K = two 8K 64-K subs.
#define H_A   0
#define H_BG  16384
#define H_BU  32768
#define H_STG 49152
#define H_TOT (2 * H_STG)

#define H_LOADFRAG(ks, fa_, fbg_, fbu_) { \
    uint32_t subOff = ((ks) >> 2) * 8192; \
    uint32_t kk = ((ks) & 3) * 32; \
    LDMX4(fbg_, sb + H_BG + subOff + SWZ((uint32_t)(bRowB * 128 + kk + bCol))); \
    LDMX4(fbu_, sb + H_BU + subOff + SWZ((uint32_t)(bRowB * 128 + kk + bCol))); \
    LDMX4(fa_[0], sb + H_A + subOff + SWZ((uint32_t)(aRowB * 128 + kk + aCol))); \
    LDMX4(fa_[1], sb + H_A + subOff + SWZ((uint32_t)((aRowB + 16) * 128 + kk + aCol))); \
}

__global__ void __launch_bounds__(256, 2) hidden_gemm() {
    extern __shared__ char sm[];
    int tid = threadIdx.x, lane = tid & 31, wid = tid >> 5;
    int wm = wid >> 2, wn = wid & 3;
    int z = blockIdx.z, bx = blockIdx.x;
    int m0 = blockIdx.y * 64;
    bool routed = (z > 0);

    const __half *Bg, *Bu;
    __half *H;
    int ldOut, cRowBase, mValid;
    const int K = DIM;

    int aRow = tid >> 2, aQ = tid & 3;     // loader: 64 rows, 4 thr/row, 64B each
    int aRowLd;

    if (!routed) {
        Bg = d_Wgs; Bu = d_Wus;
        H = d_Hs; ldOut = DS;
        mValid = 64; cRowBase = m0;
        aRowLd = m0 + aRow;
    } else {
        if (bx >= DE / 64) return;
        int e = z - 1;
        int cnt = d_ecnt[e], off = e * ECAP;
        if (m0 >= cnt) return;
        size_t wb = (size_t)e * DE * DIM;
        Bg = d_Wge + wb; Bu = d_Wue + wb;
        H = d_Hr; ldOut = DE;
        mValid = cnt - m0; if (mValid > 64) mValid = 64;
        cRowBase = off + m0;
        int m = m0 + aRow; if (m > cnt - 1) m = cnt - 1;
        aRowLd = d_etok[off + m];
    }
    int n0 = bx * 64;

    uint32_t sbase = sm2u32(sm);
    const char* aG  = (const char*)(d_x + (size_t)aRowLd * DIM) + aQ * 64;
    const char* bgP = (const char*)(Bg + (size_t)(n0 + aRow) * K) + aQ * 64;
    const char* buP = (const char*)(Bu + (size_t)(n0 + aRow) * K) + aQ * 64;
    uint32_t sL[4];   // smem store offsets (relative to stage base, per array)
    #pragma unroll
    for (int j = 0; j < 4; j++)
        sL[j] = (aQ >> 1) * 8192 + SWZ((uint32_t)(aRow * 128 + (aQ & 1) * 64 + j * 16));

    const int nStg = K / 128;   // 8

    // prologue: stage 0 <- K-bytes [0,256)
    {
        uint32_t sb = sbase;
        #pragma unroll
        for (int j = 0; j < 4; j++) {
            CPA16(sb + H_A  + sL[j], aG  + j * 16);
            CPA16(sb + H_BG + sL[j], bgP + j * 16);
            CPA16(sb + H_BU + sL[j], buP + j * 16);
        }
        CPCOMMIT();
    }

    float ag[2][2][4], au[2][2][4];
    #pragma unroll
    for (int a = 0; a < 2; a++)
        #pragma unroll
        for (int b = 0; b < 2; b++)
            #pragma unroll
            for (int cR = 0; cR < 4; cR++) { ag[a][b][cR] = 0.f; au[a][b][cR] = 0.f; }

    int aRowB = wm * 32 + (lane & 15);
    uint32_t aCol = ((lane >> 4) & 1) * 16;
    int bRowB = wn * 16 + (lane & 7) + ((lane >> 4) << 3);
    uint32_t bCol = ((lane >> 3) & 1) * 16;

    for (int c = 0; c < nStg; c++) {
        if (c + 1 < nStg) {
            uint32_t sb = sbase + ((c + 1) & 1) * H_STG;
            int kb = (c + 1) * 256;
            #pragma unroll
            for (int j = 0; j < 4; j++) {
                CPA16(sb + H_A  + sL[j], aG  + kb + j * 16);
                CPA16(sb + H_BG + sL[j], bgP + kb + j * 16);
                CPA16(sb + H_BU + sL[j], buP + kb + j * 16);
            }
            CPCOMMIT();
            CPWAIT1();
        } else {
            CPWAIT0();
        }
        __syncthreads();

        uint32_t sb = sbase + (c & 1) * H_STG;
        uint32_t fa[2][2][4], fbg[2][4], fbu[2][4];
        H_LOADFRAG(0, fa[0], fbg[0], fbu[0]);
        #pragma unroll
        for (int ks = 0; ks < 8; ks++) {
            int cur = ks & 1;
            if (ks < 7) H_LOADFRAG(ks + 1, fa[cur ^ 1], fbg[cur ^ 1], fbu[cur ^ 1]);
            #pragma unroll
            for (int mt = 0; mt < 2; mt++) {
                #pragma unroll
                for (int n8 = 0; n8 < 2; n8++) {
                    int j = n8 * 2;
                    MMAF16(ag[mt][n8], fa[cur][mt], fbg[cur][j], fbg[cur][j + 1]);
                    MMAF16(au[mt][n8], fa[cur][mt], fbu[cur][j], fbu[cur][j + 1]);
                }
            }
        }
        __syncthreads();
    }

    #pragma unroll
    for (int mt = 0; mt < 2; mt++) {
        #pragma unroll
        for (int h = 0; h < 2; h++) {
            int rIn = wm * 32 + mt * 16 + (lane >> 2) + h * 8;
            if (rIn < mValid) {
                float wt = routed ? d_ewt[cRowBase + rIn] : 1.0f;
                size_t rowOff = (size_t)(cRowBase + rIn) * ldOut;
                #pragma unroll
                for (int n8 = 0; n8 < 2; n8++) {
                    int col = n0 + wn * 16 + n8 * 8 + (lane & 3) * 2;
                    float v0 = wt * silu(ag[mt][n8][h * 2 + 0]) * au[mt][n8][h * 2 + 0];
                    float v1 = wt * silu(ag[mt][n8][h * 2 + 1]) * au[mt][n8][h * 2 + 1];
                    __half2 hv; hv.x = __float2half(v0); hv.y = __float2half(v1);
                    *(__half2*)(H + rowOff + col) = hv;
                }
            }
        }
    }
}

// ---------------- down GEMM ----------------
// CTA tile M64 x N128; 8 warps 2x4, warp 32x32.
// stage: [A 16K (two 8K subs)][B 32K (two 16K subs)] = 48K.
#define D_A   0
#define D_B   16384
#define D_STG 49152
#define D_TOT (2 * D_STG)

#define D_LOADFRAG(ks, fa_, fb_) { \
    uint32_t kk = ((ks) & 3) * 32; \
    uint32_t subA = sb + D_A + ((ks) >> 2) * 8192; \
    uint32_t subB = sb + D_B + ((ks) >> 2) * 16384; \
    LDMX4(fb_[0], subB + SWZ((uint32_t)(bRowB * 128 + kk + bCol))); \
    LDMX4(fb_[1], subB + SWZ((uint32_t)((bRowB + 16) * 128 + kk + bCol))); \
    LDMX4(fa_[0], subA + SWZ((uint32_t)(aRowB * 128 + kk + aCol))); \
    LDMX4(fa_[1], subA + SWZ((uint32_t)((aRowB + 16) * 128 + kk + aCol))); \
}

__global__ void __launch_bounds__(256, 2) down_gemm(float* __restrict__ out) {
    extern __shared__ char sm[];
    int tid = threadIdx.x, lane = tid & 31, wid = tid >> 5;
    int wm = wid >> 2, wn = wid & 3;
    int z = blockIdx.z;
    int m0 = blockIdx.y * 64;
    bool routed = (z > 0);

    const __half *A, *B;
    float* C;
    int K, mValid, cRowBase, aRowLd;

    int aRow = tid >> 2, aQ = tid & 3;     // A loader: 64 rows, 4 thr/row, 64B
    int bRow = tid >> 1, bH = tid & 1;     // B loader: 128 rows, 2 thr/row, 128B

    if (!routed) {
        A = d_Hs; K = DS;
        B = d_Wds;
        C = out;
        mValid = 64; cRowBase = m0;
        aRowLd = m0 + aRow;
    } else {
        int e = z - 1;
        int cnt = d_ecnt[e], off = e * ECAP;
        if (m0 >= cnt) return;
        A = d_Hr; K = DE;
        B = d_Wde + (size_t)e * DIM * DE;
        C = d_R;
        mValid = cnt - m0; if (mValid > 64) mValid = 64;
        cRowBase = off + m0;
        int m = m0 + aRow; if (m > cnt - 1) m = cnt - 1;
        aRowLd = off + m;
    }
    int n0 = blockIdx.x * 128;

    uint32_t sbase = sm2u32(sm);
    const char* aG = (const char*)(A + (size_t)aRowLd * K) + aQ * 64;
    const char* bG = (const char*)(B + (size_t)(n0 + bRow) * K) + bH * 128;
    uint32_t sA[4], sB[8];
    #pragma unroll
    for (int j = 0; j < 4; j++)
        sA[j] = D_A + (aQ >> 1) * 8192 + SWZ((uint32_t)(aRow * 128 + (aQ & 1) * 64 + j * 16));
    #pragma unroll
    for (int j = 0; j < 8; j++)
        sB[j] = D_B + bH * 16384 + SWZ((uint32_t)(bRow * 128 + j * 16));

    int nStg = K / 128;    // dense 8, routed 4

    // prologue: stage 0
    {
        uint32_t sb = sbase;
        #pragma unroll
        for (int j = 0; j < 4; j++) CPA16(sb + sA[j], aG + j * 16);
        #pragma unroll
        for (int j = 0; j < 8; j++) CPA16(sb + sB[j], bG + j * 16);
        CPCOMMIT();
    }

    float acc[2][4][4];
    #pragma unroll
    for (int a = 0; a < 2; a++)
        #pragma unroll
        for (int b = 0; b < 4; b++)
            #pragma unroll
            for (int cR = 0; cR < 4; cR++) acc[a][b][cR] = 0.f;

    int aRowB = wm * 32 + (lane & 15);
    uint32_t aCol = ((lane >> 4) & 1) * 16;
    int bRowB = wn * 32 + (lane & 7) + ((lane >> 4) << 3);
    uint32_t bCol = ((lane >> 3) & 1) * 16;

    for (int c = 0; c < nStg; c++) {
        if (c + 1 < nStg) {
            uint32_t sb = sbase + ((c + 1) & 1) * D_STG;
            int kb = (c + 1) * 256;
            #pragma unroll
            for (int j = 0; j < 4; j++) CPA16(sb + sA[j], aG + kb + j * 16);
            #pragma unroll
            for (int j = 0; j < 8; j++) CPA16(sb + sB[j], bG + kb + j * 16);
            CPCOMMIT();
            CPWAIT1();
        } else {
            CPWAIT0();
        }
        __syncthreads();

        uint32_t sb = sbase + (c & 1) * D_STG;
        uint32_t fa[2][2][4], fb[2][2][4];
        D_LOADFRAG(0, fa[0], fb[0]);
        #pragma unroll
        for (int ks = 0; ks < 8; ks++) {
            int cur = ks & 1;
            if (ks < 7) D_LOADFRAG(ks + 1, fa[cur ^ 1], fb[cur ^ 1]);
            #pragma unroll
            for (int mt = 0; mt < 2; mt++) {
                #pragma unroll
                for (int n8 = 0; n8 < 4; n8++) {
                    int g = n8 >> 1, j = (n8 & 1) * 2;
                    MMAF16(acc[mt][n8], fa[cur][mt], fb[cur][g][j], fb[cur][g][j + 1]);
                }
            }
        }
        __syncthreads();
    }

    #pragma unroll
    for (int mt = 0; mt < 2; mt++) {
        #pragma unroll
        for (int h = 0; h < 2; h++) {
            int rIn = wm * 32 + mt * 16 + (lane >> 2) + h * 8;
            if (rIn < mValid) {
                float* p = C + (size_t)(cRowBase + rIn) * DIM + n0 + wn * 32 + (lane & 3) * 2;
                #pragma unroll
                for (int n8 = 0; n8 < 4; n8++) {
                    float2 v; v.x = acc[mt][n8][h * 2 + 0]; v.y = acc[mt][n8][h * 2 + 1];
                    *(float2*)(p + n8 * 8) = v;
                }
            }
        }
    }
}

// ----------------- launch -----------------
extern "C" void kernel_launch(void* const* d_in, const int* in_sizes, int n_in,
                              void* d_out, int out_size) {
    const float* x   = (const float*)d_in[0];
    const float* Wg  = (const float*)d_in[1];
    const float* Wge = (const float*)d_in[2];
    const float* Wue = (const float*)d_in[3];
    const float* Wde = (const float*)d_in[4];
    const float* Wgs = (const float*)d_in[5];
    const float* Wus = (const float*)d_in[6];
    const float* Wds = (const float*)d_in[7];
    float* out = (float*)d_out;

    cudaFuncSetAttribute(hidden_gemm, cudaFuncAttributeMaxDynamicSharedMemorySize, H_TOT);
    cudaFuncSetAttribute(down_gemm,   cudaFuncAttributeMaxDynamicSharedMemorySize, D_TOT);

    void* ecnt_ptr;
    cudaGetSymbolAddress(&ecnt_ptr, d_ecnt);
    cudaMemsetAsync(ecnt_ptr, 0, NE * sizeof(int), 0);

    convT_all<<<15360, dim3(32, 8)>>>(Wgs, Wus, Wds, Wge, Wue, Wde);     // 1
    gate_kernel<<<N_TOK, 256>>>(x, Wg);                                  // 2
    hidden_gemm<<<dim3(16, 32, 9), 256, H_TOT>>>();                      // 3
    down_gemm<<<dim3(8, 32, 9), 256, D_TOT>>>(out);                      // 4  <- profiled
    combine_kernel<<<N_TOK, 256>>>(out);                                 // 5
}

// round 14
// speedup vs baseline: 1.2198x; 1.2198x over previous
#include <cuda_runtime.h>
#include <cuda_fp16.h>
#include <math.h>
#include <stdint.h>

#define N_TOK 2048
#define DIM   1024
#define DE    512
#define DS    1024
#define NE    8
#define NSLOT (N_TOK * 2)
#define ECAP  2048

// ----------------- scratch (device globals; no allocs) -----------------
__device__ int   d_ecnt[NE];                 // zeroed via cudaMemsetAsync
__device__ int   d_etok[NE * ECAP];
__device__ float d_ewt [NE * ECAP];
__device__ int   d_slot[NSLOT];

__device__ __half d_x  [N_TOK * DIM];                     // x fp16
__device__ __half d_Wgs[DS * DIM];                        // weights fp16, [N][K]
__device__ __half d_Wus[DS * DIM];
__device__ __half d_Wds[DIM * DS];
__device__ __half d_Wge[NE * DE * DIM];
__device__ __half d_Wue[NE * DE * DIM];
__device__ __half d_Wde[NE * DIM * DE];

__device__ __half d_Hs[N_TOK * DS];
__device__ __half d_Hr[NE * ECAP * DE];
__device__ float d_R [NE * ECAP * DIM];

// ----------------- asm helpers -----------------
__device__ __forceinline__ uint32_t sm2u32(const void* p) {
    uint32_t a;
    asm("{ .reg .u64 t; cvta.to.shared.u64 t, %1; cvt.u32.u64 %0, t; }" : "=r"(a) : "l"(p));
    return a;
}
#define SWZ(o) ((o) ^ (((o) >> 3) & 0x70))

#define CPA16(s, g)  asm volatile("cp.async.cg.shared.global [%0], [%1], 16;" :: "r"(s), "l"(g))
#define CPCOMMIT()   asm volatile("cp.async.commit_group;" ::: "memory")
#define CPWAIT1()    asm volatile("cp.async.wait_group 1;" ::: "memory")
#define CPWAIT0()    asm volatile("cp.async.wait_group 0;" ::: "memory")

#define LDMX4(r, a) \
    asm volatile("ldmatrix.sync.aligned.m8n8.x4.shared.b16 {%0,%1,%2,%3}, [%4];" \
        : "=r"((r)[0]), "=r"((r)[1]), "=r"((r)[2]), "=r"((r)[3]) : "r"(a))

#define MMAF16(c, a, b0, b1) \
    asm volatile("mma.sync.aligned.m16n8k16.row.col.f32.f16.f16.f32 " \
        "{%0,%1,%2,%3},{%4,%5,%6,%7},{%8,%9},{%0,%1,%2,%3};" \
        : "+f"((c)[0]), "+f"((c)[1]), "+f"((c)[2]), "+f"((c)[3]) \
        : "r"((a)[0]), "r"((a)[1]), "r"((a)[2]), "r"((a)[3]), "r"(b0), "r"(b1))

// ----------------- gate + convX + routing (fused) -----------------
__global__ void gate_kernel(const float* __restrict__ x, const float* __restrict__ Wg) {
    int n = blockIdx.x;
    int t = threadIdx.x;
    __shared__ float xs[DIM];
    __shared__ float logits[NE];
    float4 v = ((const float4*)(x + (size_t)n * DIM))[t];
    ((float4*)xs)[t] = v;
    {
        __half2 a, b;
        a.x = __float2half(v.x); a.y = __float2half(v.y);
        b.x = __float2half(v.z); b.y = __float2half(v.w);
        size_t o = (size_t)n * DIM + t * 4;
        *(__half2*)(d_x + o) = a; *(__half2*)(d_x + o + 2) = b;
    }
    __syncthreads();
    int w = t >> 5, l = t & 31;
    float s = 0.f;
    for (int d = l; d < DIM; d += 32) s += xs[d] * Wg[d * NE + w];
    #pragma unroll
    for (int o = 16; o; o >>= 1) s += __shfl_xor_sync(0xffffffffu, s, o);
    if (l == 0) logits[w] = s;
    __syncthreads();
    if (t == 0) {
        float mx = logits[0];
        #pragma unroll
        for (int e = 1; e < NE; e++) mx = fmaxf(mx, logits[e]);
        float p[NE], den = 0.f;
        #pragma unroll
        for (int e = 0; e < NE; e++) { p[e] = expf(logits[e] - mx); den += p[e]; }
        float inv = 1.f / den;
        int i0 = 0;
        #pragma unroll
        for (int e = 1; e < NE; e++) if (p[e] > p[i0]) i0 = e;
        int i1 = (i0 == 0) ? 1 : 0;
        #pragma unroll
        for (int e = 0; e < NE; e++) if (e != i0 && p[e] > p[i1]) i1 = e;
        int p0 = atomicAdd(&d_ecnt[i0], 1);
        int s0 = i0 * ECAP + p0;
        d_etok[s0] = n; d_ewt[s0] = p[i0] * inv; d_slot[2*n] = s0;
        int p1 = atomicAdd(&d_ecnt[i1], 1);
        int s1 = i1 * ECAP + p1;
        d_etok[s1] = n; d_ewt[s1] = p[i1] * inv; d_slot[2*n+1] = s1;
    }
}

// weight transposes, one launch: src [K][N] fp32 -> [N][K] fp16
__global__ void convT_all(const float* __restrict__ Wgs, const float* __restrict__ Wus,
                          const float* __restrict__ Wds, const float* __restrict__ Wge,
                          const float* __restrict__ Wue, const float* __restrict__ Wde) {
    int id = blockIdx.x;
    const float* src; __half* dh; int K, N, tile;
    if (id < 1024)      { src = Wgs; dh = d_Wgs; K = DIM; N = DS;  tile = id; }
    else if (id < 2048) { src = Wus; dh = d_Wus; K = DIM; N = DS;  tile = id - 1024; }
    else if (id < 3072) { src = Wds; dh = d_Wds; K = DS;  N = DIM; tile = id - 2048; }
    else if (id < 7168) {
        int l = id - 3072; int b = l >> 9; tile = l & 511; K = DIM; N = DE;
        src = Wge + (size_t)b * DIM * DE; dh = d_Wge + (size_t)b * DE * DIM;
    } else if (id < 11264) {
        int l = id - 7168; int b = l >> 9; tile = l & 511; K = DIM; N = DE;
        src = Wue + (size_t)b * DIM * DE; dh = d_Wue + (size_t)b * DE * DIM;
    } else {
        int l = id - 11264; int b = l >> 9; tile = l & 511; K = DE; N = DIM;
        src = Wde + (size_t)b * DE * DIM; dh = d_Wde + (size_t)b * DIM * DE;
    }
    int tilesX = N / 32;
    int n0 = (tile % tilesX) * 32, k0 = (tile / tilesX) * 32;
    __shared__ float t[32][33];
    int tx = threadIdx.x, ty = threadIdx.y;
    #pragma unroll
    for (int i = 0; i < 32; i += 8) t[ty + i][tx] = src[(size_t)(k0 + ty + i) * N + n0 + tx];
    __syncthreads();
    #pragma unroll
    for (int i = 0; i < 32; i += 8) {
        dh[(size_t)(n0 + ty + i) * K + k0 + tx] = __float2half(t[tx][ty + i]);
    }
}

__device__ __forceinline__ float silu(float g) { return g * (1.f / (1.f + expf(-g))); }

__global__ void combine_kernel(float* __restrict__ out) {
    int n = blockIdx.x;
    int t = threadIdx.x;
    int s0 = d_slot[2 * n], s1 = d_slot[2 * n + 1];
    float4* o4 = (float4*)(out + (size_t)n * DIM);
    const float4* r0 = (const float4*)(d_R + (size_t)s0 * DIM);
    const float4* r1 = (const float4*)(d_R + (size_t)s1 * DIM);
    float4 a = o4[t], b = r0[t], c = r1[t];
    a.x += b.x + c.x; a.y += b.y + c.y; a.z += b.z + c.z; a.w += b.w + c.w;
    o4[t] = a;
}

// ============================================================
// GEMMs: pure fp16 (fp32 accum). M-tile 64, 24KB/stage, 3-stage
// cp.async, 3 CTAs/SM, SINGLE barrier per K-chunk:
//   wait -> bar -> prefetch(c+2) -> compute(c)
// (barrier proves all warps finished reading the stage that the
//  prefetch overwrites; it also publishes chunk c's cp.async data)
// ============================================================

// ---------------- hidden GEMM ----------------
// CTA tile M64 x N64 per matrix (g,u); 8 warps 2x4, warp 32x16 per matrix.
#define H_A   0
#define H_BG  8192
#define H_BU  16384
#define H_STG 24576
#define H_TOT (3 * H_STG)

__global__ void __launch_bounds__(256, 3) hidden_gemm() {
    extern __shared__ char sm[];
    int tid = threadIdx.x, lane = tid & 31, wid = tid >> 5;
    int wm = wid >> 2, wn = wid & 3;
    int z = blockIdx.z, bx = blockIdx.x;
    int m0 = blockIdx.y * 64;
    bool routed = (z > 0);

    const __half *Bg, *Bu;
    __half *H;
    int ldOut, cRowBase, mValid;
    const int K = DIM;

    int aRow = tid >> 2, aQ = tid & 3;        // loaders: 64 rows, 4 thr/row (32B each)
    int aRowLd;

    if (!routed) {
        Bg = d_Wgs; Bu = d_Wus;
        H = d_Hs; ldOut = DS;
        mValid = 64; cRowBase = m0;
        aRowLd = m0 + aRow;
    } else {
        if (bx >= DE / 64) return;
        int e = z - 1;
        int cnt = d_ecnt[e], off = e * ECAP;
        if (m0 >= cnt) return;
        size_t wb = (size_t)e * DE * DIM;
        Bg = d_Wge + wb; Bu = d_Wue + wb;
        H = d_Hr; ldOut = DE;
        mValid = cnt - m0; if (mValid > 64) mValid = 64;
        cRowBase = off + m0;
        int m = m0 + aRow; if (m > cnt - 1) m = cnt - 1;
        aRowLd = d_etok[off + m];
    }
    int n0 = bx * 64;

    uint32_t sbase = sm2u32(sm);
    const char* aG  = (const char*)(d_x + (size_t)aRowLd * DIM) + aQ * 32;
    const char* bgP = (const char*)(Bg + (size_t)(n0 + aRow) * K) + aQ * 32;
    const char* buP = (const char*)(Bu + (size_t)(n0 + aRow) * K) + aQ * 32;
    uint32_t sA[2];
    #pragma unroll
    for (int j = 0; j < 2; j++) sA[j] = SWZ((uint32_t)(aRow * 128 + aQ * 32 + j * 16));

    const int nChunks = K / 64;

    // prologue: stages 0,1 <- chunks 0,1
    #pragma unroll
    for (int c = 0; c < 2; c++) {
        uint32_t sb = sbase + c * H_STG;
        int kb = c * 128;
        #pragma unroll
        for (int j = 0; j < 2; j++) {
            CPA16(sb + H_A  + sA[j], aG  + kb + j * 16);
            CPA16(sb + H_BG + sA[j], bgP + kb + j * 16);
            CPA16(sb + H_BU + sA[j], buP + kb + j * 16);
        }
        CPCOMMIT();
    }

    float ag[2][2][4], au[2][2][4];
    #pragma unroll
    for (int a = 0; a < 2; a++)
        #pragma unroll
        for (int b = 0; b < 2; b++)
            #pragma unroll
            for (int cR = 0; cR < 4; cR++) { ag[a][b][cR] = 0.f; au[a][b][cR] = 0.f; }

    int aRowB = wm * 32 + (lane & 15);
    uint32_t aCol = ((lane >> 4) & 1) * 16;
    int bRowB = wn * 16 + (lane & 7) + ((lane >> 4) << 3);
    uint32_t bCol = ((lane >> 3) & 1) * 16;

    int st = 0;
    for (int c = 0; c < nChunks; c++) {
        if (c + 1 < nChunks) { CPWAIT1(); } else { CPWAIT0(); }
        __syncthreads();                          // single barrier per chunk
        if (c + 2 < nChunks) {
            int pf = (st == 0) ? 2 : st - 1;      // (c+2)%3
            uint32_t sb = sbase + pf * H_STG;
            int kb = (c + 2) * 128;
            #pragma unroll
            for (int j = 0; j < 2; j++) {
                CPA16(sb + H_A  + sA[j], aG  + kb + j * 16);
                CPA16(sb + H_BG + sA[j], bgP + kb + j * 16);
                CPA16(sb + H_BU + sA[j], buP + kb + j * 16);
            }
            CPCOMMIT();
        }

        uint32_t sb = sbase + st * H_STG;
        #pragma unroll
        for (int ks = 0; ks < 4; ks++) {
            uint32_t bg[4], bu[4];
            {
                uint32_t rb = (uint32_t)(bRowB * 128 + ks * 32 + bCol);
                LDMX4(bg, sb + H_BG + SWZ(rb));
                LDMX4(bu, sb + H_BU + SWZ(rb));
            }
            #pragma unroll
            for (int mt = 0; mt < 2; mt++) {
                uint32_t a[4];
                uint32_t rb = (uint32_t)((aRowB + mt * 16) * 128 + ks * 32 + aCol);
                LDMX4(a, sb + H_A + SWZ(rb));
                #pragma unroll
                for (int n8 = 0; n8 < 2; n8++) {
                    int j = n8 * 2;
                    MMAF16(ag[mt][n8], a, bg[j], bg[j + 1]);
                    MMAF16(au[mt][n8], a, bu[j], bu[j + 1]);
                }
            }
        }
        st = (st == 2) ? 0 : st + 1;
    }

    #pragma unroll
    for (int mt = 0; mt < 2; mt++) {
        #pragma unroll
        for (int h = 0; h < 2; h++) {
            int rIn = wm * 32 + mt * 16 + (lane >> 2) + h * 8;
            if (rIn < mValid) {
                float wt = routed ? d_ewt[cRowBase + rIn] : 1.0f;
                size_t rowOff = (size_t)(cRowBase + rIn) * ldOut;
                #pragma unroll
                for (int n8 = 0; n8 < 2; n8++) {
                    int col = n0 + wn * 16 + n8 * 8 + (lane & 3) * 2;
                    float v0 = wt * silu(ag[mt][n8][h * 2 + 0]) * au[mt][n8][h * 2 + 0];
                    float v1 = wt * silu(ag[mt][n8][h * 2 + 1]) * au[mt][n8][h * 2 + 1];
                    __half2 hv; hv.x = __float2half(v0); hv.y = __float2half(v1);
                    *(__half2*)(H + rowOff + col) = hv;
                }
            }
        }
    }
}

// ---------------- down GEMM ----------------
// CTA tile M64 x N128; 8 warps 2x4, warp 32x32. z=0 dense -> out; z>0 routed -> R.
#define D_A   0
#define D_B   8192
#define D_STG 24576
#define D_TOT (3 * D_STG)

__global__ void __launch_bounds__(256, 3) down_gemm(float* __restrict__ out) {
    extern __shared__ char sm[];
    int tid = threadIdx.x, lane = tid & 31, wid = tid >> 5;
    int wm = wid >> 2, wn = wid & 3;
    int z = blockIdx.z;
    int m0 = blockIdx.y * 64;
    bool routed = (z > 0);

    const __half *A, *B;
    float* C;
    int K, mValid, cRowBase, aRowLd;

    int aRow = tid >> 2, aQ = tid & 3;        // A: 64 rows, 4 thr/row
    int bRow = tid >> 1, bHalf = tid & 1;     // B: 128 rows, 2 thr/row

    if (!routed) {
        A = d_Hs; K = DS;
        B = d_Wds;
        C = out;
        mValid = 64; cRowBase = m0;
        aRowLd = m0 + aRow;
    } else {
        int e = z - 1;
        int cnt = d_ecnt[e], off = e * ECAP;
        if (m0 >= cnt) return;
        A = d_Hr; K = DE;
        B = d_Wde + (size_t)e * DIM * DE;
        C = d_R;
        mValid = cnt - m0; if (mValid > 64) mValid = 64;
        cRowBase = off + m0;
        int m = m0 + aRow; if (m > cnt - 1) m = cnt - 1;
        aRowLd = off + m;
    }
    int n0 = blockIdx.x * 128;

    uint32_t sbase = sm2u32(sm);
    const char* aG = (const char*)(A + (size_t)aRowLd * K) + aQ * 32;
    const char* bG = (const char*)(B + (size_t)(n0 + bRow) * K) + bHalf * 64;
    uint32_t sA[2], sB[4];
    #pragma unroll
    for (int j = 0; j < 2; j++) sA[j] = SWZ((uint32_t)(aRow * 128 + aQ * 32 + j * 16));
    #pragma unroll
    for (int j = 0; j < 4; j++) sB[j] = SWZ((uint32_t)(bRow * 128 + bHalf * 64 + j * 16));

    int nChunks = K / 64;

    #pragma unroll
    for (int c = 0; c < 2; c++) {
        uint32_t sb = sbase + c * D_STG;
        int kb = c * 128;
        #pragma unroll
        for (int j = 0; j < 2; j++) CPA16(sb + D_A + sA[j], aG + kb + j * 16);
        #pragma unroll
        for (int j = 0; j < 4; j++) CPA16(sb + D_B + sB[j], bG + kb + j * 16);
        CPCOMMIT();
    }

    float acc[2][4][4];
    #pragma unroll
    for (int a = 0; a < 2; a++)
        #pragma unroll
        for (int b = 0; b < 4; b++)
            #pragma unroll
            for (int cR = 0; cR < 4; cR++) acc[a][b][cR] = 0.f;

    int aRowB = wm * 32 + (lane & 15);
    uint32_t aCol = ((lane >> 4) & 1) * 16;
    int bRowB = wn * 32 + (lane & 7) + ((lane >> 4) << 3);
    uint32_t bCol = ((lane >> 3) & 1) * 16;

    int st = 0;
    for (int c = 0; c < nChunks; c++) {
        if (c + 1 < nChunks) { CPWAIT1(); } else { CPWAIT0(); }
        __syncthreads();                          // single barrier per chunk
        if (c + 2 < nChunks) {
            int pf = (st == 0) ? 2 : st - 1;
            uint32_t sb = sbase + pf * D_STG;
            int kb = (c + 2) * 128;
            #pragma unroll
            for (int j = 0; j < 2; j++) CPA16(sb + D_A + sA[j], aG + kb + j * 16);
            #pragma unroll
            for (int j = 0; j < 4; j++) CPA16(sb + D_B + sB[j], bG + kb + j * 16);
            CPCOMMIT();
        }

        uint32_t sb = sbase + st * D_STG;
        #pragma unroll
        for (int ks = 0; ks < 4; ks++) {
            uint32_t b[2][4];
            #pragma unroll
            for (int g = 0; g < 2; g++) {
                uint32_t rb = (uint32_t)((bRowB + g * 16) * 128 + ks * 32 + bCol);
                LDMX4(b[g], sb + D_B + SWZ(rb));
            }
            #pragma unroll
            for (int mt = 0; mt < 2; mt++) {
                uint32_t a[4];
                uint32_t rb = (uint32_t)((aRowB + mt * 16) * 128 + ks * 32 + aCol);
                LDMX4(a, sb + D_A + SWZ(rb));
                #pragma unroll
                for (int n8 = 0; n8 < 4; n8++) {
                    int g = n8 >> 1, j = (n8 & 1) * 2;
                    MMAF16(acc[mt][n8], a, b[g][j], b[g][j + 1]);
                }
            }
        }
        st = (st == 2) ? 0 : st + 1;
    }

    #pragma unroll
    for (int mt = 0; mt < 2; mt++) {
        #pragma unroll
        for (int h = 0; h < 2; h++) {
            int rIn = wm * 32 + mt * 16 + (lane >> 2) + h * 8;
            if (rIn < mValid) {
                float* p = C + (size_t)(cRowBase + rIn) * DIM + n0 + wn * 32 + (lane & 3) * 2;
                #pragma unroll
                for (int n8 = 0; n8 < 4; n8++) {
                    float2 v; v.x = acc[mt][n8][h * 2 + 0]; v.y = acc[mt][n8][h * 2 + 1];
                    *(float2*)(p + n8 * 8) = v;
                }
            }
        }
    }
}

// ----------------- launch -----------------
extern "C" void kernel_launch(void* const* d_in, const int* in_sizes, int n_in,
                              void* d_out, int out_size) {
    const float* x   = (const float*)d_in[0];
    const float* Wg  = (const float*)d_in[1];
    const float* Wge = (const float*)d_in[2];
    const float* Wue = (const float*)d_in[3];
    const float* Wde = (const float*)d_in[4];
    const float* Wgs = (const float*)d_in[5];
    const float* Wus = (const float*)d_in[6];
    const float* Wds = (const float*)d_in[7];
    float* out = (float*)d_out;

    cudaFuncSetAttribute(hidden_gemm, cudaFuncAttributeMaxDynamicSharedMemorySize, H_TOT);
    cudaFuncSetAttribute(down_gemm,   cudaFuncAttributeMaxDynamicSharedMemorySize, D_TOT);

    void* ecnt_ptr;
    cudaGetSymbolAddress(&ecnt_ptr, d_ecnt);
    cudaMemsetAsync(ecnt_ptr, 0, NE * sizeof(int), 0);

    convT_all<<<15360, dim3(32, 8)>>>(Wgs, Wus, Wds, Wge, Wue, Wde);     // 1
    gate_kernel<<<N_TOK, 256>>>(x, Wg);                                  // 2
    hidden_gemm<<<dim3(16, 32, 9), 256, H_TOT>>>();                      // 3
    down_gemm<<<dim3(8, 32, 9), 256, D_TOT>>>(out);                      // 4  <- profiled
    combine_kernel<<<N_TOK, 256>>>(out);                                 // 5
}

// round 17
// speedup vs baseline: 1.2499x; 1.0248x over previous
#include <cuda_runtime.h>
#include <cuda_fp16.h>
#include <math.h>
#include <stdint.h>

#define N_TOK 2048
#define DIM   1024
#define DE    512
#define DS    1024
#define NE    8
#define NSLOT (N_TOK * 2)
#define ECAP  2048

// ----------------- scratch (device globals; no allocs) -----------------
__device__ int   d_ecnt[NE];                 // zeroed via cudaMemsetAsync
__device__ int   d_etok[NE * ECAP];
__device__ float d_ewt [NE * ECAP];
__device__ int   d_slot[NSLOT];

__device__ __half d_x  [N_TOK * DIM];                     // x fp16
__device__ __half d_Wgs[DS * DIM];                        // weights fp16, [N][K]
__device__ __half d_Wus[DS * DIM];
__device__ __half d_Wds[DIM * DS];
__device__ __half d_Wge[NE * DE * DIM];
__device__ __half d_Wue[NE * DE * DIM];
__device__ __half d_Wde[NE * DIM * DE];

__device__ __half d_Hs[N_TOK * DS];
__device__ __half d_Hr[NE * ECAP * DE];
__device__ float d_R [NE * ECAP * DIM];

// ----------------- asm helpers -----------------
__device__ __forceinline__ uint32_t sm2u32(const void* p) {
    uint32_t a;
    asm("{ .reg .u64 t; cvta.to.shared.u64 t, %1; cvt.u32.u64 %0, t; }" : "=r"(a) : "l"(p));
    return a;
}
#define SWZ(o) ((o) ^ (((o) >> 3) & 0x70))

#define CPA16(s, g)  asm volatile("cp.async.cg.shared.global [%0], [%1], 16;" :: "r"(s), "l"(g))
#define CPCOMMIT()   asm volatile("cp.async.commit_group;" ::: "memory")
#define CPWAIT1()    asm volatile("cp.async.wait_group 1;" ::: "memory")
#define CPWAIT0()    asm volatile("cp.async.wait_group 0;" ::: "memory")

#define LDMX4(r, a) \
    asm volatile("ldmatrix.sync.aligned.m8n8.x4.shared.b16 {%0,%1,%2,%3}, [%4];" \
        : "=r"((r)[0]), "=r"((r)[1]), "=r"((r)[2]), "=r"((r)[3]) : "r"(a))

#define MMAF16(c, a, b0, b1) \
    asm volatile("mma.sync.aligned.m16n8k16.row.col.f32.f16.f16.f32 " \
        "{%0,%1,%2,%3},{%4,%5,%6,%7},{%8,%9},{%0,%1,%2,%3};" \
        : "+f"((c)[0]), "+f"((c)[1]), "+f"((c)[2]), "+f"((c)[3]) \
        : "r"((a)[0]), "r"((a)[1]), "r"((a)[2]), "r"((a)[3]), "r"(b0), "r"(b1))

// ----------------- gate + convX + routing (fused) -----------------
__global__ void gate_kernel(const float* __restrict__ x, const float* __restrict__ Wg) {
    int n = blockIdx.x;
    int t = threadIdx.x;
    __shared__ float xs[DIM];
    __shared__ float logits[NE];
    float4 v = ((const float4*)(x + (size_t)n * DIM))[t];
    ((float4*)xs)[t] = v;
    {
        __half2 a, b;
        a.x = __float2half(v.x); a.y = __float2half(v.y);
        b.x = __float2half(v.z); b.y = __float2half(v.w);
        size_t o = (size_t)n * DIM + t * 4;
        *(__half2*)(d_x + o) = a; *(__half2*)(d_x + o + 2) = b;
    }
    __syncthreads();
    int w = t >> 5, l = t & 31;
    float s = 0.f;
    for (int d = l; d < DIM; d += 32) s += xs[d] * Wg[d * NE + w];
    #pragma unroll
    for (int o = 16; o; o >>= 1) s += __shfl_xor_sync(0xffffffffu, s, o);
    if (l == 0) logits[w] = s;
    __syncthreads();
    if (t == 0) {
        float mx = logits[0];
        #pragma unroll
        for (int e = 1; e < NE; e++) mx = fmaxf(mx, logits[e]);
        float p[NE], den = 0.f;
        #pragma unroll
        for (int e = 0; e < NE; e++) { p[e] = expf(logits[e] - mx); den += p[e]; }
        float inv = 1.f / den;
        int i0 = 0;
        #pragma unroll
        for (int e = 1; e < NE; e++) if (p[e] > p[i0]) i0 = e;
        int i1 = (i0 == 0) ? 1 : 0;
        #pragma unroll
        for (int e = 0; e < NE; e++) if (e != i0 && p[e] > p[i1]) i1 = e;
        int p0 = atomicAdd(&d_ecnt[i0], 1);
        int s0 = i0 * ECAP + p0;
        d_etok[s0] = n; d_ewt[s0] = p[i0] * inv; d_slot[2*n] = s0;
        int p1 = atomicAdd(&d_ecnt[i1], 1);
        int s1 = i1 * ECAP + p1;
        d_etok[s1] = n; d_ewt[s1] = p[i1] * inv; d_slot[2*n+1] = s1;
    }
}

// weight transposes, one launch, 64x64 tiles: src [K][N] fp32 -> [N][K] fp16
__global__ void convT_all(const float* __restrict__ Wgs, const float* __restrict__ Wus,
                          const float* __restrict__ Wds, const float* __restrict__ Wge,
                          const float* __restrict__ Wue, const float* __restrict__ Wde) {
    int id = blockIdx.x;
    const float* src; __half* dh; int K, N, tile;
    if (id < 256)       { src = Wgs; dh = d_Wgs; K = DIM; N = DS;  tile = id; }
    else if (id < 512)  { src = Wus; dh = d_Wus; K = DIM; N = DS;  tile = id - 256; }
    else if (id < 768)  { src = Wds; dh = d_Wds; K = DS;  N = DIM; tile = id - 512; }
    else if (id < 1792) {
        int l = id - 768; int b = l >> 7; tile = l & 127; K = DIM; N = DE;
        src = Wge + (size_t)b * DIM * DE; dh = d_Wge + (size_t)b * DE * DIM;
    } else if (id < 2816) {
        int l = id - 1792; int b = l >> 7; tile = l & 127; K = DIM; N = DE;
        src = Wue + (size_t)b * DIM * DE; dh = d_Wue + (size_t)b * DE * DIM;
    } else {
        int l = id - 2816; int b = l >> 7; tile = l & 127; K = DE; N = DIM;
        src = Wde + (size_t)b * DE * DIM; dh = d_Wde + (size_t)b * DIM * DE;
    }
    int tilesX = N / 64;
    int n0 = (tile % tilesX) * 64, k0 = (tile / tilesX) * 64;
    __shared__ float t[64][65];
    int tx = threadIdx.x, ty = threadIdx.y;    // 32 x 8
    #pragma unroll
    for (int i = 0; i < 64; i += 8) {
        const float* r = src + (size_t)(k0 + ty + i) * N + n0;
        t[ty + i][tx]      = r[tx];
        t[ty + i][tx + 32] = r[tx + 32];
    }
    __syncthreads();
    #pragma unroll
    for (int i = 0; i < 64; i += 8) {
        int nn = ty + i;
        __half2 h;
        h.x = __float2half(t[tx * 2][nn]);
        h.y = __float2half(t[tx * 2 + 1][nn]);
        *(__half2*)(dh + (size_t)(n0 + nn) * K + k0 + tx * 2) = h;
    }
}

__device__ __forceinline__ float silu(float g) { return g * (1.f / (1.f + expf(-g))); }

__global__ void combine_kernel(float* __restrict__ out) {
    int n = blockIdx.x;
    int t = threadIdx.x;
    int s0 = d_slot[2 * n], s1 = d_slot[2 * n + 1];
    float4* o4 = (float4*)(out + (size_t)n * DIM);
    const float4* r0 = (const float4*)(d_R + (size_t)s0 * DIM);
    const float4* r1 = (const float4*)(d_R + (size_t)s1 * DIM);
    float4 a = o4[t], b = r0[t], c = r1[t];
    a.x += b.x + c.x; a.y += b.y + c.y; a.z += b.z + c.z; a.w += b.w + c.w;
    o4[t] = a;
}

// ============================================================
// GEMMs: pure fp16 (fp32 accum). M-tile 64, 24KB/stage, 3-stage
// cp.async, 3 CTAs/SM, single barrier per K-chunk.
// down_gemm additionally double-buffers B fragments (regs paid for
// by recomputing cp.async store offsets in the prefetch).
// ============================================================

// ---------------- hidden GEMM (unchanged from best) ----------------
#define H_A   0
#define H_BG  8192
#define H_BU  16384
#define H_STG 24576
#define H_TOT (3 * H_STG)

__global__ void __launch_bounds__(256, 3) hidden_gemm() {
    extern __shared__ char sm[];
    int tid = threadIdx.x, lane = tid & 31, wid = tid >> 5;
    int wm = wid >> 2, wn = wid & 3;
    int z = blockIdx.z, bx = blockIdx.x;
    int m0 = blockIdx.y * 64;
    bool routed = (z > 0);

    const __half *Bg, *Bu;
    __half *H;
    int ldOut, cRowBase, mValid;
    const int K = DIM;

    int aRow = tid >> 2, aQ = tid & 3;
    int aRowLd;

    if (!routed) {
        Bg = d_Wgs; Bu = d_Wus;
        H = d_Hs; ldOut = DS;
        mValid = 64; cRowBase = m0;
        aRowLd = m0 + aRow;
    } else {
        if (bx >= DE / 64) return;
        int e = z - 1;
        int cnt = d_ecnt[e], off = e * ECAP;
        if (m0 >= cnt) return;
        size_t wb = (size_t)e * DE * DIM;
        Bg = d_Wge + wb; Bu = d_Wue + wb;
        H = d_Hr; ldOut = DE;
        mValid = cnt - m0; if (mValid > 64) mValid = 64;
        cRowBase = off + m0;
        int m = m0 + aRow; if (m > cnt - 1) m = cnt - 1;
        aRowLd = d_etok[off + m];
    }
    int n0 = bx * 64;

    uint32_t sbase = sm2u32(sm);
    const char* aG  = (const char*)(d_x + (size_t)aRowLd * DIM) + aQ * 32;
    const char* bgP = (const char*)(Bg + (size_t)(n0 + aRow) * K) + aQ * 32;
    const char* buP = (const char*)(Bu + (size_t)(n0 + aRow) * K) + aQ * 32;
    uint32_t sA[2];
    #pragma unroll
    for (int j = 0; j < 2; j++) sA[j] = SWZ((uint32_t)(aRow * 128 + aQ * 32 + j * 16));

    const int nChunks = K / 64;

    #pragma unroll
    for (int c = 0; c < 2; c++) {
        uint32_t sb = sbase + c * H_STG;
        int kb = c * 128;
        #pragma unroll
        for (int j = 0; j < 2; j++) {
            CPA16(sb + H_A  + sA[j], aG  + kb + j * 16);
            CPA16(sb + H_BG + sA[j], bgP + kb + j * 16);
            CPA16(sb + H_BU + sA[j], buP + kb + j * 16);
        }
        CPCOMMIT();
    }

    float ag[2][2][4], au[2][2][4];
    #pragma unroll
    for (int a = 0; a < 2; a++)
        #pragma unroll
        for (int b = 0; b < 2; b++)
            #pragma unroll
            for (int cR = 0; cR < 4; cR++) { ag[a][b][cR] = 0.f; au[a][b][cR] = 0.f; }

    int aRowB = wm * 32 + (lane & 15);
    uint32_t aCol = ((lane >> 4) & 1) * 16;
    int bRowB = wn * 16 + (lane & 7) + ((lane >> 4) << 3);
    uint32_t bCol = ((lane >> 3) & 1) * 16;

    int st = 0;
    for (int c = 0; c < nChunks; c++) {
        if (c + 1 < nChunks) { CPWAIT1(); } else { CPWAIT0(); }
        __syncthreads();
        if (c + 2 < nChunks) {
            int pf = (st == 0) ? 2 : st - 1;
            uint32_t sb = sbase + pf * H_STG;
            int kb = (c + 2) * 128;
            #pragma unroll
            for (int j = 0; j < 2; j++) {
                CPA16(sb + H_A  + sA[j], aG  + kb + j * 16);
                CPA16(sb + H_BG + sA[j], bgP + kb + j * 16);
                CPA16(sb + H_BU + sA[j], buP + kb + j * 16);
            }
            CPCOMMIT();
        }

        uint32_t sb = sbase + st * H_STG;
        #pragma unroll
        for (int ks = 0; ks < 4; ks++) {
            uint32_t bg[4], bu[4];
            {
                uint32_t rb = (uint32_t)(bRowB * 128 + ks * 32 + bCol);
                LDMX4(bg, sb + H_BG + SWZ(rb));
                LDMX4(bu, sb + H_BU + SWZ(rb));
            }
            #pragma unroll
            for (int mt = 0; mt < 2; mt++) {
                uint32_t a[4];
                uint32_t rb = (uint32_t)((aRowB + mt * 16) * 128 + ks * 32 + aCol);
                LDMX4(a, sb + H_A + SWZ(rb));
                #pragma unroll
                for (int n8 = 0; n8 < 2; n8++) {
                    int j = n8 * 2;
                    MMAF16(ag[mt][n8], a, bg[j], bg[j + 1]);
                    MMAF16(au[mt][n8], a, bu[j], bu[j + 1]);
                }
            }
        }
        st = (st == 2) ? 0 : st + 1;
    }

    #pragma unroll
    for (int mt = 0; mt < 2; mt++) {
        #pragma unroll
        for (int h = 0; h < 2; h++) {
            int rIn = wm * 32 + mt * 16 + (lane >> 2) + h * 8;
            if (rIn < mValid) {
                float wt = routed ? d_ewt[cRowBase + rIn] : 1.0f;
                size_t rowOff = (size_t)(cRowBase + rIn) * ldOut;
                #pragma unroll
                for (int n8 = 0; n8 < 2; n8++) {
                    int col = n0 + wn * 16 + n8 * 8 + (lane & 3) * 2;
                    float v0 = wt * silu(ag[mt][n8][h * 2 + 0]) * au[mt][n8][h * 2 + 0];
                    float v1 = wt * silu(ag[mt][n8][h * 2 + 1]) * au[mt][n8][h * 2 + 1];
                    __half2 hv; hv.x = __float2half(v0); hv.y = __float2half(v1);
                    *(__half2*)(H + rowOff + col) = hv;
                }
            }
        }
    }
}

// ---------------- down GEMM (B-frag double-buffered) ----------------
#define D_A   0
#define D_B   8192
#define D_STG 24576
#define D_TOT (3 * D_STG)

#define D_LOADB(kss, dst) { \
    uint32_t rb0 = (uint32_t)(bRowB * 128 + (kss) * 32 + bCol); \
    LDMX4((dst)[0], sb + D_B + SWZ(rb0)); \
    uint32_t rb1 = (uint32_t)((bRowB + 16) * 128 + (kss) * 32 + bCol); \
    LDMX4((dst)[1], sb + D_B + SWZ(rb1)); \
}

__global__ void __launch_bounds__(256, 3) down_gemm(float* __restrict__ out) {
    extern __shared__ char sm[];
    int tid = threadIdx.x, lane = tid & 31, wid = tid >> 5;
    int wm = wid >> 2, wn = wid & 3;
    int z = blockIdx.z;
    int m0 = blockIdx.y * 64;
    bool routed = (z > 0);

    const __half *A, *B;
    float* C;
    int K, mValid, cRowBase, aRowLd;

    int aRow = tid >> 2, aQ = tid & 3;        // A: 64 rows, 4 thr/row
    int bRow = tid >> 1, bHalf = tid & 1;     // B: 128 rows, 2 thr/row

    if (!routed) {
        A = d_Hs; K = DS;
        B = d_Wds;
        C = out;
        mValid = 64; cRowBase = m0;
        aRowLd = m0 + aRow;
    } else {
        int e = z - 1;
        int cnt = d_ecnt[e], off = e * ECAP;
        if (m0 >= cnt) return;
        A = d_Hr; K = DE;
        B = d_Wde + (size_t)e * DIM * DE;
        C = d_R;
        mValid = cnt - m0; if (mValid > 64) mValid = 64;
        cRowBase = off + m0;
        int m = m0 + aRow; if (m > cnt - 1) m = cnt - 1;
        aRowLd = off + m;
    }
    int n0 = blockIdx.x * 128;

    uint32_t sbase = sm2u32(sm);
    const char* aG = (const char*)(A + (size_t)aRowLd * K) + aQ * 32;
    const char* bG = (const char*)(B + (size_t)(n0 + bRow) * K) + bHalf * 64;
    uint32_t sA[2];
    #pragma unroll
    for (int j = 0; j < 2; j++) sA[j] = SWZ((uint32_t)(aRow * 128 + aQ * 32 + j * 16));

    int nChunks = K / 64;

    #pragma unroll
    for (int c = 0; c < 2; c++) {
        uint32_t sb = sbase + c * D_STG;
        int kb = c * 128;
        #pragma unroll
        for (int j = 0; j < 2; j++) CPA16(sb + D_A + sA[j], aG + kb + j * 16);
        #pragma unroll
        for (int j = 0; j < 4; j++) {
            uint32_t sB = SWZ((uint32_t)(bRow * 128 + bHalf * 64 + j * 16));
            CPA16(sb + D_B + sB, bG + kb + j * 16);
        }
        CPCOMMIT();
    }

    float acc[2][4][4];
    #pragma unroll
    for (int a = 0; a < 2; a++)
        #pragma unroll
        for (int b = 0; b < 4; b++)
            #pragma unroll
            for (int cR = 0; cR < 4; cR++) acc[a][b][cR] = 0.f;

    int aRowB = wm * 32 + (lane & 15);
    uint32_t aCol = ((lane >> 4) & 1) * 16;
    int bRowB = wn * 32 + (lane & 7) + ((lane >> 4) << 3);
    uint32_t bCol = ((lane >> 3) & 1) * 16;

    int st = 0;
    for (int c = 0; c < nChunks; c++) {
        if (c + 1 < nChunks) { CPWAIT1(); } else { CPWAIT0(); }
        __syncthreads();
        if (c + 2 < nChunks) {
            int pf = (st == 0) ? 2 : st - 1;
            uint32_t sb = sbase + pf * D_STG;
            int kb = (c + 2) * 128;
            #pragma unroll
            for (int j = 0; j < 2; j++) CPA16(sb + D_A + sA[j], aG + kb + j * 16);
            #pragma unroll
            for (int j = 0; j < 4; j++) {
                uint32_t sB = SWZ((uint32_t)(bRow * 128 + bHalf * 64 + j * 16));
                CPA16(sb + D_B + sB, bG + kb + j * 16);
            }
            CPCOMMIT();
        }

        uint32_t sb = sbase + st * D_STG;
        uint32_t bf[2][2][4];
        D_LOADB(0, bf[0]);
        #pragma unroll
        for (int ks = 0; ks < 4; ks++) {
            int cur = ks & 1;
            if (ks < 3) D_LOADB(ks + 1, bf[cur ^ 1]);
            #pragma unroll
            for (int mt = 0; mt < 2; mt++) {
                uint32_t a[4];
                uint32_t rb = (uint32_t)((aRowB + mt * 16) * 128 + ks * 32 + aCol);
                LDMX4(a, sb + D_A + SWZ(rb));
                #pragma unroll
                for (int n8 = 0; n8 < 4; n8++) {
                    int g = n8 >> 1, j = (n8 & 1) * 2;
                    MMAF16(acc[mt][n8], a, bf[cur][g][j], bf[cur][g][j + 1]);
                }
            }
        }
        st = (st == 2) ? 0 : st + 1;
    }

    #pragma unroll
    for (int mt = 0; mt < 2; mt++) {
        #pragma unroll
        for (int h = 0; h < 2; h++) {
            int rIn = wm * 32 + mt * 16 + (lane >> 2) + h * 8;
            if (rIn < mValid) {
                float* p = C + (size_t)(cRowBase + rIn) * DIM + n0 + wn * 32 + (lane & 3) * 2;
                #pragma unroll
                for (int n8 = 0; n8 < 4; n8++) {
                    float2 v; v.x = acc[mt][n8][h * 2 + 0]; v.y = acc[mt][n8][h * 2 + 1];
                    *(float2*)(p + n8 * 8) = v;
                }
            }
        }
    }
}

// ----------------- launch -----------------
extern "C" void kernel_launch(void* const* d_in, const int* in_sizes, int n_in,
                              void* d_out, int out_size) {
    const float* x   = (const float*)d_in[0];
    const float* Wg  = (const float*)d_in[1];
    const float* Wge = (const float*)d_in[2];
    const float* Wue = (const float*)d_in[3];
    const float* Wde = (const float*)d_in[4];
    const float* Wgs = (const float*)d_in[5];
    const float* Wus = (const float*)d_in[6];
    const float* Wds = (const float*)d_in[7];
    float* out = (float*)d_out;

    cudaFuncSetAttribute(hidden_gemm, cudaFuncAttributeMaxDynamicSharedMemorySize, H_TOT);
    cudaFuncSetAttribute(down_gemm,   cudaFuncAttributeMaxDynamicSharedMemorySize, D_TOT);

    void* ecnt_ptr;
    cudaGetSymbolAddress(&ecnt_ptr, d_ecnt);
    cudaMemsetAsync(ecnt_ptr, 0, NE * sizeof(int), 0);

    convT_all<<<3840, dim3(32, 8)>>>(Wgs, Wus, Wds, Wge, Wue, Wde);      // 1
    gate_kernel<<<N_TOK, 256>>>(x, Wg);                                  // 2
    hidden_gemm<<<dim3(16, 32, 9), 256, H_TOT>>>();                      // 3
    down_gemm<<<dim3(8, 32, 9), 256, D_TOT>>>(out);                      // 4  <- profiled
    combine_kernel<<<N_TOK, 256>>>(out);                                 // 5
}